// round 1
// baseline (speedup 1.0000x reference)
#include <cuda_runtime.h>

// Problem constants
#define B_     16
#define L_     1024
#define D_     256        // INPUT_SIZE
#define PAST_  16
#define LQ_    (L_ - PAST_)   // 1008
#define NL_    3

#define O_ELEMS   ((size_t)B_ * LQ_ * 256)   // 4,128,768 floats

// ---- Kernel 1: fused 3-layer dilated attention ----
#define TL    64
#define HALO  7
#define ROWS  (TL + HALO)   // 71

// scratch: post-attention activations (rules: no cudaMalloc -> __device__ array)
__device__ float g_mid[(size_t)B_ * L_ * D_];

__global__ void __launch_bounds__(256)
attn_kernel(const float* __restrict__ inp, float* __restrict__ attn_out)
{
    extern __shared__ float sm[];
    __shared__ float a0s[ROWS], a1s[ROWS];
    float* buf0 = sm;                // ROWS * D_
    float* buf1 = sm + ROWS * D_;    // ROWS * D_

    const int b     = blockIdx.y;
    const int t     = blockIdx.x;
    const int start = t * TL;
    const int tid   = threadIdx.x;
    const int warp  = tid >> 5;
    const int lane  = tid & 31;

    // Load tile rows [start-7, start+64) ; zero-fill rows with l < 0
    const float* inb = inp + (size_t)b * L_ * D_;
    for (int idx = tid; idx < ROWS * (D_ / 4); idx += 256) {
        int h = idx >> 6;         // 64 float4 per row
        int q = idx & 63;
        int l = start - HALO + h;
        float4 v = make_float4(0.f, 0.f, 0.f, 0.f);
        if (l >= 0) v = ((const float4*)(inb + (size_t)l * D_))[q];
        ((float4*)(buf0 + h * D_))[q] = v;
    }
    __syncthreads();

    float* cur = buf0;
    float* nxt = buf1;

    #pragma unroll
    for (int layer = 0; layer < NL_; layer++) {
        const int d    = 1 << layer;
        const int hmin = 2 * d - 1;   // 1, 3, 7

        // --- per-row 2-dot + 2-way softmax (one warp per row) ---
        for (int h = hmin + warp; h < ROWS; h += 8) {
            const float* r0 = cur + h * D_;
            const float* r1 = cur + (h - d) * D_;
            float p0 = 0.f, p1 = 0.f;
            #pragma unroll
            for (int k = lane; k < D_; k += 32) {
                float x = r0[k];
                p0 = fmaf(x, x, p0);
                p1 = fmaf(x, r1[k], p1);
            }
            #pragma unroll
            for (int o = 16; o; o >>= 1) {
                p0 += __shfl_xor_sync(0xffffffffu, p0, o);
                p1 += __shfl_xor_sync(0xffffffffu, p1, o);
            }
            int l = start - HALO + h;
            float a0 = 1.f, a1 = 0.f;
            if (l >= d) {
                float s0 = p0 * 0.0625f;   // scale = 1/sqrt(256)
                float s1 = p1 * 0.0625f;
                float m  = fmaxf(s0, s1);
                float e0 = expf(s0 - m);
                float e1 = expf(s1 - m);
                float inv = 1.f / (e0 + e1);
                a0 = e0 * inv;
                a1 = e1 * inv;
            }
            if (lane == 0) { a0s[h] = a0; a1s[h] = a1; }
        }
        __syncthreads();

        // --- residual update: nxt[h] = (a0*cur[h] + a1*cur[h-d]) + cur[h] ---
        // one column per thread (tid = column), loop rows
        for (int h = hmin; h < ROWS; h++) {
            float x = cur[h * D_ + tid];
            float y = cur[(h - d) * D_ + tid];
            nxt[h * D_ + tid] = fmaf(a0s[h], x, a1s[h] * y) + x;
        }

        // --- write full attn rows for own 64 rows (zeros + 2 nonzeros) ---
        float* abase = attn_out + (size_t)(b * NL_ + layer) * L_ * L_;
        for (int idx = tid; idx < TL * (L_ / 4); idx += 256) {
            int r = idx >> 8;          // 256 float4 per 1024-wide row
            int q = idx & 255;
            int l = start + r;
            int h = r + HALO;
            float4 v = make_float4(0.f, 0.f, 0.f, 0.f);
            float* vp = (float*)&v;
            int c0 = l;
            int c1 = l - d;
            if ((c0 >> 2) == q)              vp[c0 & 3] = a0s[h];
            if (c1 >= 0 && (c1 >> 2) == q)   vp[c1 & 3] = a1s[h];
            ((float4*)(abase + (size_t)l * L_))[q] = v;
        }
        __syncthreads();

        float* tmp = cur; cur = nxt; nxt = tmp;
    }

    // --- write final activations for own rows to scratch ---
    float* gout = g_mid + ((size_t)b * L_ + start) * D_;
    for (int idx = tid; idx < TL * (D_ / 4); idx += 256) {
        int r = idx >> 6;
        int q = idx & 63;
        ((float4*)(gout + r * D_))[q] = ((const float4*)(cur + (r + HALO) * D_))[q];
    }
}

// ---- Kernel 2: o = mid[:, 16:] @ W^T + bias + residual ----
// M = 16*1008 = 16128, N = 256, K = 256
#define BM 64
#define BK 64
#define AS_STRIDE 65     // pad: avoids transpose-store conflicts
#define WS_STRIDE 257    // pad: conflict-free strided column reads

__global__ void __launch_bounds__(256)
gemm_kernel(const float* __restrict__ W, const float* __restrict__ bias,
            const float* __restrict__ inp, float* __restrict__ o_out)
{
    extern __shared__ float sm[];
    float* As = sm;                      // [BK][AS_STRIDE] : As[k][row]
    float* Ws = sm + BK * AS_STRIDE;     // [BK][WS_STRIDE] : Ws[k][col]

    const int tid = threadIdx.x;
    const int m0  = blockIdx.x * BM;
    const int rg  = tid >> 5;    // 8 row-groups: rows rg*8 .. rg*8+7
    const int cg  = tid & 31;    // cols cg + 32*j, j=0..7

    float acc[8][8];
    #pragma unroll
    for (int i = 0; i < 8; i++)
        #pragma unroll
        for (int j = 0; j < 8; j++) acc[i][j] = 0.f;

    for (int kc = 0; kc < 256; kc += BK) {
        __syncthreads();
        // Load A tile (transpose to k-major)
        for (int idx = tid; idx < BM * (BK / 4); idx += 256) {
            int r  = idx >> 4;
            int kq = idx & 15;
            int m  = m0 + r;
            int bb = m / LQ_;
            int l  = m - bb * LQ_ + PAST_;
            float4 v = *(const float4*)(g_mid + ((size_t)bb * L_ + l) * D_ + kc + kq * 4);
            As[(kq * 4 + 0) * AS_STRIDE + r] = v.x;
            As[(kq * 4 + 1) * AS_STRIDE + r] = v.y;
            As[(kq * 4 + 2) * AS_STRIDE + r] = v.z;
            As[(kq * 4 + 3) * AS_STRIDE + r] = v.w;
        }
        // Load W tile (transpose to k-major)
        for (int idx = tid; idx < 256 * (BK / 4); idx += 256) {
            int oc = idx >> 4;
            int kq = idx & 15;
            float4 v = *(const float4*)(W + oc * 256 + kc + kq * 4);
            Ws[(kq * 4 + 0) * WS_STRIDE + oc] = v.x;
            Ws[(kq * 4 + 1) * WS_STRIDE + oc] = v.y;
            Ws[(kq * 4 + 2) * WS_STRIDE + oc] = v.z;
            Ws[(kq * 4 + 3) * WS_STRIDE + oc] = v.w;
        }
        __syncthreads();

        #pragma unroll 4
        for (int kk = 0; kk < BK; kk++) {
            float a[8], w[8];
            #pragma unroll
            for (int i = 0; i < 8; i++) a[i] = As[kk * AS_STRIDE + rg * 8 + i];  // broadcast in warp
            #pragma unroll
            for (int j = 0; j < 8; j++) w[j] = Ws[kk * WS_STRIDE + cg + 32 * j]; // conflict-free
            #pragma unroll
            for (int i = 0; i < 8; i++)
                #pragma unroll
                for (int j = 0; j < 8; j++)
                    acc[i][j] = fmaf(a[i], w[j], acc[i][j]);
        }
    }

    // Epilogue: + bias + residual inp[b, lq+16, col & 63]
    #pragma unroll
    for (int i = 0; i < 8; i++) {
        int m  = m0 + rg * 8 + i;
        int bb = m / LQ_;
        int lq = m - bb * LQ_;
        const float* res = inp + ((size_t)bb * L_ + lq + PAST_) * D_;
        float* orow = o_out + (size_t)m * 256;
        #pragma unroll
        for (int j = 0; j < 8; j++) {
            int col = cg + 32 * j;
            orow[col] = acc[i][j] + bias[col] + res[col & 63];
        }
    }
}

extern "C" void kernel_launch(void* const* d_in, const int* in_sizes, int n_in,
                              void* d_out, int out_size)
{
    const float* inp  = (const float*)d_in[0];
    const float* W    = (const float*)d_in[1];
    const float* bias = (const float*)d_in[2];
    // d_in[3] = masks : structure is known at compile time, unused

    float* out  = (float*)d_out;           // o : (16, 1008, 4, 64)
    float* attn = out + O_ELEMS;           // attn_stack : (16, 3, 1024, 1024)

    const int smem1 = 2 * ROWS * D_ * (int)sizeof(float);                       // 145,408 B
    const int smem2 = (BK * AS_STRIDE + BK * WS_STRIDE) * (int)sizeof(float);   // 82,432 B
    cudaFuncSetAttribute(attn_kernel, cudaFuncAttributeMaxDynamicSharedMemorySize, smem1);
    cudaFuncSetAttribute(gemm_kernel, cudaFuncAttributeMaxDynamicSharedMemorySize, smem2);

    attn_kernel<<<dim3(L_ / TL, B_), 256, smem1>>>(inp, attn);
    gemm_kernel<<<(B_ * LQ_) / BM, 256, smem2>>>(W, bias, inp, out);
}

// round 2
// speedup vs baseline: 1.2765x; 1.2765x over previous
#include <cuda_runtime.h>
#include <cstdint>

// Problem constants
#define B_     16
#define L_     1024
#define D_     256        // INPUT_SIZE
#define PAST_  16
#define LQ_    (L_ - PAST_)   // 1008
#define NL_    3

#define O_ELEMS   ((size_t)B_ * LQ_ * 256)   // 4,128,768 floats

// ---- scratch (__device__ arrays: no cudaMalloc allowed) ----
__device__ float g_mid[(size_t)B_ * L_ * D_];                 // post-attn activations
__device__ float g_coef[(size_t)B_ * NL_ * L_ * 2];           // (a0, a1) per row

// =====================================================================
// Kernel 1: fused 3-layer dilated attention -> coefficients + g_mid
// =====================================================================
#define TL    64
#define HALO  7
#define ROWS  (TL + HALO)   // 71

__global__ void __launch_bounds__(256)
attn_compute_kernel(const float* __restrict__ inp)
{
    extern __shared__ float sm[];
    __shared__ float a0s[ROWS], a1s[ROWS];
    float* buf0 = sm;                // ROWS * D_
    float* buf1 = sm + ROWS * D_;    // ROWS * D_

    const int b     = blockIdx.y;
    const int t     = blockIdx.x;
    const int start = t * TL;
    const int tid   = threadIdx.x;
    const int warp  = tid >> 5;
    const int lane  = tid & 31;

    // Load tile rows [start-7, start+64); zero-fill rows with l < 0
    const float* inb = inp + (size_t)b * L_ * D_;
    for (int idx = tid; idx < ROWS * (D_ / 4); idx += 256) {
        int h = idx >> 6;
        int q = idx & 63;
        int l = start - HALO + h;
        float4 v = make_float4(0.f, 0.f, 0.f, 0.f);
        if (l >= 0) v = ((const float4*)(inb + (size_t)l * D_))[q];
        ((float4*)(buf0 + h * D_))[q] = v;
    }
    __syncthreads();

    float* cur = buf0;
    float* nxt = buf1;

    #pragma unroll
    for (int layer = 0; layer < NL_; layer++) {
        const int d    = 1 << layer;
        const int hmin = 2 * d - 1;   // 1, 3, 7

        // per-row 2-dot + 2-way softmax (one warp per row)
        for (int h = hmin + warp; h < ROWS; h += 8) {
            const float* r0 = cur + h * D_;
            const float* r1 = cur + (h - d) * D_;
            float p0 = 0.f, p1 = 0.f;
            #pragma unroll
            for (int k = lane; k < D_; k += 32) {
                float x = r0[k];
                p0 = fmaf(x, x, p0);
                p1 = fmaf(x, r1[k], p1);
            }
            #pragma unroll
            for (int o = 16; o; o >>= 1) {
                p0 += __shfl_xor_sync(0xffffffffu, p0, o);
                p1 += __shfl_xor_sync(0xffffffffu, p1, o);
            }
            int l = start - HALO + h;
            float a0 = 1.f, a1 = 0.f;
            if (l >= d) {
                float s0 = p0 * 0.0625f;
                float s1 = p1 * 0.0625f;
                float m  = fmaxf(s0, s1);
                float e0 = expf(s0 - m);
                float e1 = expf(s1 - m);
                float inv = 1.f / (e0 + e1);
                a0 = e0 * inv;
                a1 = e1 * inv;
            }
            if (lane == 0) { a0s[h] = a0; a1s[h] = a1; }
        }
        __syncthreads();

        // residual update in smem
        for (int h = hmin; h < ROWS; h++) {
            float x = cur[h * D_ + tid];
            float y = cur[(h - d) * D_ + tid];
            nxt[h * D_ + tid] = fmaf(a0s[h], x, a1s[h] * y) + x;
        }

        // write coefficients for own rows
        if (tid < TL) {
            int l = start + tid;
            float* cp = g_coef + ((size_t)(b * NL_ + layer) * L_ + l) * 2;
            cp[0] = a0s[HALO + tid];
            cp[1] = a1s[HALO + tid];
        }
        __syncthreads();

        float* tmp = cur; cur = nxt; nxt = tmp;
    }

    // write final activations
    float* gout = g_mid + ((size_t)b * L_ + start) * D_;
    for (int idx = tid; idx < TL * (D_ / 4); idx += 256) {
        int r = idx >> 6;
        int q = idx & 63;
        ((float4*)(gout + r * D_))[q] = ((const float4*)(cur + (r + HALO) * D_))[q];
    }
}

// =====================================================================
// Kernel 2: stream attn_stack rows (zeros with 2 injected values)
// one warp per 4KB row, STG.128 only
// =====================================================================
#define FILL_BLOCKS 1184   // 148 * 8

__global__ void __launch_bounds__(256)
attn_fill_kernel(float* __restrict__ attn_out)
{
    const int lane   = threadIdx.x & 31;
    const int gwarp  = (blockIdx.x << 3) + (threadIdx.x >> 5);
    const int nwarps = FILL_BLOCKS * 8;
    const int nrows  = B_ * NL_ * L_;   // 49152

    for (int row = gwarp; row < nrows; row += nwarps) {
        const int l     = row & (L_ - 1);
        const int layer = (row >> 10) % NL_;
        const int d     = 1 << layer;

        const float* cp = g_coef + (size_t)row * 2;
        const float a0 = cp[0];
        const float a1 = cp[1];
        const int c0 = l;
        const int c1 = l - d;

        float4* dst = (float4*)(attn_out + (size_t)row * L_);
        #pragma unroll
        for (int s = 0; s < 8; s++) {
            int q = lane + (s << 5);       // float4 index within row
            float4 v = make_float4(0.f, 0.f, 0.f, 0.f);
            if ((c0 >> 2) == q)              ((float*)&v)[c0 & 3] = a0;
            if (c1 >= 0 && (c1 >> 2) == q)   ((float*)&v)[c1 & 3] = a1;
            dst[q] = v;
        }
    }
}

// =====================================================================
// Kernel 3: o = g_mid[:,16:] @ W^T + bias + residual   (tf32 mma.sync)
// M=16128, N=256, K=256 ; block tile 128x64, BK=32, 8 warps of 32x32
// =====================================================================
#define GBM 128
#define GBN 64
#define GBK 32
#define SST 36    // smem row stride (floats): bank = 4*gid + tig, conflict-free

__device__ __forceinline__ unsigned f2tf32(float x) {
    unsigned u;
    asm("cvt.rna.tf32.f32 %0, %1;" : "=r"(u) : "f"(x));
    return u;
}

__device__ __forceinline__ void mma_tf32(float* c, const unsigned* a, const unsigned* b) {
    asm volatile(
        "mma.sync.aligned.m16n8k8.row.col.f32.tf32.tf32.f32 "
        "{%0,%1,%2,%3}, {%4,%5,%6,%7}, {%8,%9}, {%0,%1,%2,%3};"
        : "+f"(c[0]), "+f"(c[1]), "+f"(c[2]), "+f"(c[3])
        : "r"(a[0]), "r"(a[1]), "r"(a[2]), "r"(a[3]), "r"(b[0]), "r"(b[1]));
}

__global__ void __launch_bounds__(256)
gemm_tf32_kernel(const float* __restrict__ W, const float* __restrict__ bias,
                 const float* __restrict__ inp, float* __restrict__ o_out)
{
    __shared__ unsigned As[GBM * SST];   // As[row][k]
    __shared__ unsigned Bs[GBN * SST];   // Bs[col][k]

    const int tid    = threadIdx.x;
    const int m0     = blockIdx.x * GBM;
    const int n0     = blockIdx.y * GBN;
    const int wid    = tid >> 5;
    const int lane   = tid & 31;
    const int warp_m = wid & 3;          // 4 warps in M -> 32 rows each
    const int warp_n = wid >> 2;         // 2 warps in N -> 32 cols each
    const int gid    = lane >> 2;
    const int tig    = lane & 3;

    float acc[2][4][4];
    #pragma unroll
    for (int i = 0; i < 2; i++)
        #pragma unroll
        for (int j = 0; j < 4; j++)
            #pragma unroll
            for (int k = 0; k < 4; k++) acc[i][j][k] = 0.f;

    for (int kc = 0; kc < 256; kc += GBK) {
        __syncthreads();
        // Load A tile: 128 rows x 32 k  (k-contiguous in gmem -> float4)
        #pragma unroll
        for (int it = 0; it < 4; it++) {
            int idx = tid + it * 256;        // 1024 float4 total
            int r   = idx >> 3;
            int q   = idx & 7;
            int m   = m0 + r;
            int bb  = m / LQ_;
            int l   = m - bb * LQ_ + PAST_;
            float4 v = *(const float4*)(g_mid + ((size_t)bb * L_ + l) * D_ + kc + q * 4);
            uint4 u = make_uint4(f2tf32(v.x), f2tf32(v.y), f2tf32(v.z), f2tf32(v.w));
            *(uint4*)(As + r * SST + q * 4) = u;
        }
        // Load B tile: 64 cols x 32 k
        #pragma unroll
        for (int it = 0; it < 2; it++) {
            int idx = tid + it * 256;        // 512 float4 total
            int n   = idx >> 3;
            int q   = idx & 7;
            float4 v = *(const float4*)(W + (size_t)(n0 + n) * 256 + kc + q * 4);
            uint4 u = make_uint4(f2tf32(v.x), f2tf32(v.y), f2tf32(v.z), f2tf32(v.w));
            *(uint4*)(Bs + n * SST + q * 4) = u;
        }
        __syncthreads();

        #pragma unroll
        for (int kk = 0; kk < GBK; kk += 8) {
            unsigned a[2][4], bf[4][2];
            #pragma unroll
            for (int mt = 0; mt < 2; mt++) {
                int r = warp_m * 32 + mt * 16 + gid;
                a[mt][0] = As[r * SST + kk + tig];
                a[mt][1] = As[(r + 8) * SST + kk + tig];
                a[mt][2] = As[r * SST + kk + tig + 4];
                a[mt][3] = As[(r + 8) * SST + kk + tig + 4];
            }
            #pragma unroll
            for (int nt = 0; nt < 4; nt++) {
                int c = warp_n * 32 + nt * 8 + gid;
                bf[nt][0] = Bs[c * SST + kk + tig];
                bf[nt][1] = Bs[c * SST + kk + tig + 4];
            }
            #pragma unroll
            for (int mt = 0; mt < 2; mt++)
                #pragma unroll
                for (int nt = 0; nt < 4; nt++)
                    mma_tf32(acc[mt][nt], a[mt], bf[nt]);
        }
    }

    // Epilogue: + bias + residual inp[b, lq+16, col&63]; float2 stores
    #pragma unroll
    for (int mt = 0; mt < 2; mt++) {
        #pragma unroll
        for (int half = 0; half < 2; half++) {
            int m  = m0 + warp_m * 32 + mt * 16 + gid + half * 8;
            int bb = m / LQ_;
            int lq = m - bb * LQ_;
            const float* res = inp + ((size_t)bb * L_ + lq + PAST_) * D_;
            float* orow = o_out + (size_t)m * 256;
            #pragma unroll
            for (int nt = 0; nt < 4; nt++) {
                int col = n0 + warp_n * 32 + nt * 8 + 2 * tig;
                float v0 = acc[mt][nt][half * 2 + 0] + bias[col]     + res[col & 63];
                float v1 = acc[mt][nt][half * 2 + 1] + bias[col + 1] + res[(col + 1) & 63];
                *(float2*)(orow + col) = make_float2(v0, v1);
            }
        }
    }
}

extern "C" void kernel_launch(void* const* d_in, const int* in_sizes, int n_in,
                              void* d_out, int out_size)
{
    const float* inp  = (const float*)d_in[0];
    const float* W    = (const float*)d_in[1];
    const float* bias = (const float*)d_in[2];
    // d_in[3] = masks : compile-time structure, unused

    float* out  = (float*)d_out;           // o : (16, 1008, 4, 64)
    float* attn = out + O_ELEMS;           // attn_stack : (16, 3, 1024, 1024)

    const int smem1 = 2 * ROWS * D_ * (int)sizeof(float);   // 145,408 B
    cudaFuncSetAttribute(attn_compute_kernel,
                         cudaFuncAttributeMaxDynamicSharedMemorySize, smem1);

    attn_compute_kernel<<<dim3(L_ / TL, B_), 256, smem1>>>(inp);
    attn_fill_kernel<<<FILL_BLOCKS, 256>>>(attn);
    gemm_tf32_kernel<<<dim3((B_ * LQ_) / GBM, 256 / GBN), 256>>>(W, bias, inp, out);
}

// round 3
// speedup vs baseline: 1.7500x; 1.3709x over previous
#include <cuda_runtime.h>
#include <cstdint>

// Problem constants
#define B_     16
#define L_     1024
#define D_     256
#define PAST_  16
#define LQ_    (L_ - PAST_)   // 1008
#define NL_    3

#define O_ELEMS   ((size_t)B_ * LQ_ * 256)   // 4,128,768 floats

// ---- scratch (__device__ arrays: no cudaMalloc allowed) ----
__device__ float g_mid[(size_t)B_ * L_ * D_];        // post-attn activations
__device__ float g_coef[(size_t)B_ * NL_ * L_ * 2];  // (a0, a1) per row

// =====================================================================
// Kernel 1: per-row recompute chain. One warp per output row.
// No smem, no barriers, full occupancy.
// =====================================================================

__device__ __forceinline__ void load_row8(float* x, const float* base, int r, int c)
{
    if (r >= 0) {
        float4 v0 = *(const float4*)(base + (size_t)r * D_ + c);
        float4 v1 = *(const float4*)(base + (size_t)r * D_ + c + 4);
        x[0]=v0.x; x[1]=v0.y; x[2]=v0.z; x[3]=v0.w;
        x[4]=v1.x; x[5]=v1.y; x[6]=v1.z; x[7]=v1.w;
    } else {
        #pragma unroll
        for (int k = 0; k < 8; k++) x[k] = 0.f;
    }
}

// p0 = u . u , p1 = u . v  (warp-wide, all lanes get result)
__device__ __forceinline__ void dot2(const float* u, const float* v, float& p0, float& p1)
{
    float s0 = 0.f, s1 = 0.f;
    #pragma unroll
    for (int k = 0; k < 8; k++) {
        s0 = fmaf(u[k], u[k], s0);
        s1 = fmaf(u[k], v[k], s1);
    }
    #pragma unroll
    for (int o = 16; o; o >>= 1) {
        s0 += __shfl_xor_sync(0xffffffffu, s0, o);
        s1 += __shfl_xor_sync(0xffffffffu, s1, o);
    }
    p0 = s0; p1 = s1;
}

__device__ __forceinline__ void coef2(float p0, float p1, bool valid, float& a0, float& a1)
{
    if (valid) {
        float s0 = p0 * 0.0625f;   // 1/sqrt(256)
        float s1 = p1 * 0.0625f;
        float m  = fmaxf(s0, s1);
        float e0 = expf(s0 - m);
        float e1 = expf(s1 - m);
        float inv = 1.f / (e0 + e1);
        a0 = e0 * inv;
        a1 = e1 * inv;
    } else {
        a0 = 1.f; a1 = 0.f;
    }
}

__global__ void __launch_bounds__(256)
attn_compute_kernel(const float* __restrict__ inp)
{
    const int lane = threadIdx.x & 31;
    const int row  = blockIdx.x * 8 + (threadIdx.x >> 5);  // 0..16383
    const int b    = row >> 10;
    const int l    = row & (L_ - 1);
    const float* base = inp + (size_t)b * L_ * D_;
    const int c = lane * 8;
    float* cb = g_coef + (size_t)b * NL_ * L_ * 2;

    // ---- layer 0 (d=1): out1 at rows l, l-2, l-4, l-6 ----
    float o1[4][8];
    #pragma unroll
    for (int t = 0; t < 4; t++) {
        int lh = l - 2 * t;
        float xh[8], xl[8];
        load_row8(xh, base, lh, c);
        load_row8(xl, base, lh - 1, c);
        float p0, p1; dot2(xh, xl, p0, p1);
        float a0, a1; coef2(p0, p1, lh >= 1, a0, a1);
        #pragma unroll
        for (int k = 0; k < 8; k++)
            o1[t][k] = fmaf(a0, xh[k], fmaf(a1, xl[k], xh[k]));
        if (t == 0 && lane == 0) {
            cb[(size_t)(0 * L_ + l) * 2 + 0] = a0;
            cb[(size_t)(0 * L_ + l) * 2 + 1] = a1;
        }
    }

    // ---- layer 1 (d=2): out2 at rows l, l-4 ----
    float o2[2][8];
    #pragma unroll
    for (int t = 0; t < 2; t++) {
        int lh = l - 4 * t;
        float p0, p1; dot2(o1[2 * t], o1[2 * t + 1], p0, p1);
        float b0, b1; coef2(p0, p1, lh >= 2, b0, b1);
        #pragma unroll
        for (int k = 0; k < 8; k++)
            o2[t][k] = fmaf(b0, o1[2 * t][k], fmaf(b1, o1[2 * t + 1][k], o1[2 * t][k]));
        if (t == 0 && lane == 0) {
            cb[(size_t)(1 * L_ + l) * 2 + 0] = b0;
            cb[(size_t)(1 * L_ + l) * 2 + 1] = b1;
        }
    }

    // ---- layer 2 (d=4): out3 at row l ----
    {
        float p0, p1; dot2(o2[0], o2[1], p0, p1);
        float c0, c1; coef2(p0, p1, l >= 4, c0, c1);
        float out[8];
        #pragma unroll
        for (int k = 0; k < 8; k++)
            out[k] = fmaf(c0, o2[0][k], fmaf(c1, o2[1][k], o2[0][k]));
        if (lane == 0) {
            cb[(size_t)(2 * L_ + l) * 2 + 0] = c0;
            cb[(size_t)(2 * L_ + l) * 2 + 1] = c1;
        }
        float* g = g_mid + ((size_t)b * L_ + l) * D_ + c;
        *(float4*)(g)     = make_float4(out[0], out[1], out[2], out[3]);
        *(float4*)(g + 4) = make_float4(out[4], out[5], out[6], out[7]);
    }
}

// =====================================================================
// Kernel 2: FUSED  attn_stack fill (DRAM-bound)  +  tf32 GEMM (tensor-bound)
// blocks with (bx % 8 == 0) run GEMM; the rest stream attn rows.
// =====================================================================
#define GBM 128
#define GBN 128
#define GBK 32
#define SST 36    // smem k-stride: bank = (4*gid + tig), conflict-free

#define GEMM_BLOCKS  252          // 126 (M) x 2 (N)
#define TOTAL_BLOCKS 2016         // GEMM_BLOCKS * 8
#define FILL_WARPS   ((TOTAL_BLOCKS - GEMM_BLOCKS) * 8)

__device__ __forceinline__ unsigned f2tf32(float x) {
    unsigned u;
    asm("cvt.rna.tf32.f32 %0, %1;" : "=r"(u) : "f"(x));
    return u;
}

__device__ __forceinline__ void mma_tf32(float* c, const unsigned* a, const unsigned* b) {
    asm volatile(
        "mma.sync.aligned.m16n8k8.row.col.f32.tf32.tf32.f32 "
        "{%0,%1,%2,%3}, {%4,%5,%6,%7}, {%8,%9}, {%0,%1,%2,%3};"
        : "+f"(c[0]), "+f"(c[1]), "+f"(c[2]), "+f"(c[3])
        : "r"(a[0]), "r"(a[1]), "r"(a[2]), "r"(a[3]), "r"(b[0]), "r"(b[1]));
}

__global__ void __launch_bounds__(256)
fused_fill_gemm_kernel(const float* __restrict__ W, const float* __restrict__ bias,
                       const float* __restrict__ inp, float* __restrict__ o_out,
                       float* __restrict__ attn_out)
{
    __shared__ unsigned As[GBM * SST];   // As[row][k]
    __shared__ unsigned Bs[GBN * SST];   // Bs[col][k]

    const int bx  = blockIdx.x;
    const int tid = threadIdx.x;

    if ((bx & 7) == 0) {
        // ================= GEMM path =================
        const int gb   = bx >> 3;                  // 0..251
        const int n0   = (gb >= 126) ? 128 : 0;
        const int m0   = (gb - (gb >= 126 ? 126 : 0)) * GBM;
        const int wid  = tid >> 5;
        const int lane = tid & 31;
        const int warp_m = wid & 3;    // 4 warps in M (32 rows each)
        const int warp_n = wid >> 2;   // 2 warps in N (64 cols each)
        const int gid = lane >> 2;
        const int tig = lane & 3;

        float acc[2][8][4];
        #pragma unroll
        for (int i = 0; i < 2; i++)
            #pragma unroll
            for (int j = 0; j < 8; j++)
                #pragma unroll
                for (int k = 0; k < 4; k++) acc[i][j][k] = 0.f;

        for (int kc = 0; kc < 256; kc += GBK) {
            __syncthreads();
            // A tile: 128 rows x 32 k
            #pragma unroll
            for (int it = 0; it < 4; it++) {
                int idx = tid + it * 256;
                int r   = idx >> 3;
                int q   = idx & 7;
                int m   = m0 + r;
                int bb  = m / LQ_;
                int l   = m - bb * LQ_ + PAST_;
                float4 v = *(const float4*)(g_mid + ((size_t)bb * L_ + l) * D_ + kc + q * 4);
                uint4 u = make_uint4(f2tf32(v.x), f2tf32(v.y), f2tf32(v.z), f2tf32(v.w));
                *(uint4*)(As + r * SST + q * 4) = u;
            }
            // B tile: 128 cols x 32 k
            #pragma unroll
            for (int it = 0; it < 4; it++) {
                int idx = tid + it * 256;
                int n   = idx >> 3;
                int q   = idx & 7;
                float4 v = *(const float4*)(W + (size_t)(n0 + n) * 256 + kc + q * 4);
                uint4 u = make_uint4(f2tf32(v.x), f2tf32(v.y), f2tf32(v.z), f2tf32(v.w));
                *(uint4*)(Bs + n * SST + q * 4) = u;
            }
            __syncthreads();

            #pragma unroll
            for (int kk = 0; kk < GBK; kk += 8) {
                unsigned a[2][4], bq[8][2];
                #pragma unroll
                for (int mt = 0; mt < 2; mt++) {
                    int r = warp_m * 32 + mt * 16 + gid;
                    a[mt][0] = As[r * SST + kk + tig];
                    a[mt][1] = As[(r + 8) * SST + kk + tig];
                    a[mt][2] = As[r * SST + kk + tig + 4];
                    a[mt][3] = As[(r + 8) * SST + kk + tig + 4];
                }
                #pragma unroll
                for (int nt = 0; nt < 8; nt++) {
                    int cix = warp_n * 64 + nt * 8 + gid;
                    bq[nt][0] = Bs[cix * SST + kk + tig];
                    bq[nt][1] = Bs[cix * SST + kk + tig + 4];
                }
                #pragma unroll
                for (int mt = 0; mt < 2; mt++)
                    #pragma unroll
                    for (int nt = 0; nt < 8; nt++)
                        mma_tf32(acc[mt][nt], a[mt], bq[nt]);
            }
        }

        // Epilogue: + bias + residual inp[b, lq+16, col&63]
        #pragma unroll
        for (int mt = 0; mt < 2; mt++) {
            #pragma unroll
            for (int half = 0; half < 2; half++) {
                int m  = m0 + warp_m * 32 + mt * 16 + gid + half * 8;
                int bb = m / LQ_;
                int lq = m - bb * LQ_;
                const float* res = inp + ((size_t)bb * L_ + lq + PAST_) * D_;
                float* orow = o_out + (size_t)m * 256;
                #pragma unroll
                for (int nt = 0; nt < 8; nt++) {
                    int col = n0 + warp_n * 64 + nt * 8 + 2 * tig;
                    float v0 = acc[mt][nt][half * 2 + 0] + bias[col]     + res[col & 63];
                    float v1 = acc[mt][nt][half * 2 + 1] + bias[col + 1] + res[(col + 1) & 63];
                    *(float2*)(orow + col) = make_float2(v0, v1);
                }
            }
        }
    } else {
        // ================= FILL path =================
        const int fb   = bx - (bx >> 3) - 1;       // compressed fill-block index
        const int lane = tid & 31;
        const int fwid = fb * 8 + (tid >> 5);
        const int nrows = B_ * NL_ * L_;           // 49152

        for (int row = fwid; row < nrows; row += FILL_WARPS) {
            const int l     = row & (L_ - 1);
            const int layer = (row >> 10) % NL_;
            const int d     = 1 << layer;

            const float a0 = g_coef[(size_t)row * 2 + 0];
            const float a1 = g_coef[(size_t)row * 2 + 1];
            const int c0 = l;
            const int c1 = l - d;

            float4* dst = (float4*)(attn_out + (size_t)row * L_);
            #pragma unroll
            for (int s = 0; s < 8; s++) {
                int q = lane + (s << 5);
                float4 v = make_float4(0.f, 0.f, 0.f, 0.f);
                if ((c0 >> 2) == q)              ((float*)&v)[c0 & 3] = a0;
                if (c1 >= 0 && (c1 >> 2) == q)   ((float*)&v)[c1 & 3] = a1;
                dst[q] = v;
            }
        }
    }
}

extern "C" void kernel_launch(void* const* d_in, const int* in_sizes, int n_in,
                              void* d_out, int out_size)
{
    const float* inp  = (const float*)d_in[0];
    const float* W    = (const float*)d_in[1];
    const float* bias = (const float*)d_in[2];
    // d_in[3] = masks : compile-time structure, unused

    float* out  = (float*)d_out;           // o : (16, 1008, 4, 64)
    float* attn = out + O_ELEMS;           // attn_stack : (16, 3, 1024, 1024)

    attn_compute_kernel<<<(B_ * L_) / 8, 256>>>(inp);
    fused_fill_gemm_kernel<<<TOTAL_BLOCKS, 256>>>(W, bias, inp, out, attn);
}

// round 4
// speedup vs baseline: 2.0856x; 1.1918x over previous
#include <cuda_runtime.h>
#include <cstdint>

// Problem constants
#define B_     16
#define L_     1024
#define D_     256
#define PAST_  16
#define LQ_    (L_ - PAST_)   // 1008
#define NL_    3

#define O_ELEMS   ((size_t)B_ * LQ_ * 256)   // 4,128,768 floats

// ---- scratch (__device__ array: no cudaMalloc allowed) ----
__device__ float g_mid[(size_t)B_ * L_ * D_];   // post-attn activations (written by layer-2 warps)

// =====================================================================
// helpers
// =====================================================================
__device__ __forceinline__ void load_row8(float* x, const float* base, int r, int c)
{
    if (r >= 0) {
        float4 v0 = *(const float4*)(base + (size_t)r * D_ + c);
        float4 v1 = *(const float4*)(base + (size_t)r * D_ + c + 4);
        x[0]=v0.x; x[1]=v0.y; x[2]=v0.z; x[3]=v0.w;
        x[4]=v1.x; x[5]=v1.y; x[6]=v1.z; x[7]=v1.w;
    } else {
        #pragma unroll
        for (int k = 0; k < 8; k++) x[k] = 0.f;
    }
}

// p0 = u.u , p1 = u.v  (warp-wide result in all lanes)
__device__ __forceinline__ void dot2(const float* u, const float* v, float& p0, float& p1)
{
    float s0 = 0.f, s1 = 0.f;
    #pragma unroll
    for (int k = 0; k < 8; k++) {
        s0 = fmaf(u[k], u[k], s0);
        s1 = fmaf(u[k], v[k], s1);
    }
    #pragma unroll
    for (int o = 16; o; o >>= 1) {
        s0 += __shfl_xor_sync(0xffffffffu, s0, o);
        s1 += __shfl_xor_sync(0xffffffffu, s1, o);
    }
    p0 = s0; p1 = s1;
}

__device__ __forceinline__ void coef2(float p0, float p1, bool valid, float& a0, float& a1)
{
    if (valid) {
        float s0 = p0 * 0.0625f;   // 1/sqrt(256)
        float s1 = p1 * 0.0625f;
        float m  = fmaxf(s0, s1);
        float e0 = expf(s0 - m);
        float e1 = expf(s1 - m);
        float inv = 1.f / (e0 + e1);
        a0 = e0 * inv;
        a1 = e1 * inv;
    } else {
        a0 = 1.f; a1 = 0.f;
    }
}

// =====================================================================
// Kernel 1: fused attn-chain recompute + attn_stack row fill (+ g_mid)
// One warp per attn row. No smem, no barriers, streaming stores.
// =====================================================================
__global__ void __launch_bounds__(256)
fill_kernel(const float* __restrict__ inp, float* __restrict__ attn_out)
{
    const int lane  = threadIdx.x & 31;
    const int row   = blockIdx.x * 8 + (threadIdx.x >> 5);   // 0..49151
    const int b     = row / (NL_ * L_);
    const int rem   = row - b * (NL_ * L_);
    const int layer = rem >> 10;
    const int l     = rem & (L_ - 1);
    const int d     = 1 << layer;
    const float* base = inp + (size_t)b * L_ * D_;
    const int c = lane * 8;

    float a0, a1;   // the two nonzeros of this attn row

    if (layer == 0) {
        float xh[8], xl[8];
        load_row8(xh, base, l, c);
        load_row8(xl, base, l - 1, c);
        float p0, p1; dot2(xh, xl, p0, p1);
        coef2(p0, p1, l >= 1, a0, a1);
    } else if (layer == 1) {
        float o1[2][8];
        #pragma unroll
        for (int t = 0; t < 2; t++) {
            int lh = l - 2 * t;
            float xh[8], xl[8];
            load_row8(xh, base, lh, c);
            load_row8(xl, base, lh - 1, c);
            float p0, p1; dot2(xh, xl, p0, p1);
            float b0, b1; coef2(p0, p1, lh >= 1, b0, b1);
            #pragma unroll
            for (int k = 0; k < 8; k++)
                o1[t][k] = fmaf(b0, xh[k], fmaf(b1, xl[k], xh[k]));
        }
        float p0, p1; dot2(o1[0], o1[1], p0, p1);
        coef2(p0, p1, l >= 2, a0, a1);
    } else {
        // full 3-layer chain; this warp also owns the g_mid row
        float o1[4][8];
        #pragma unroll
        for (int t = 0; t < 4; t++) {
            int lh = l - 2 * t;
            float xh[8], xl[8];
            load_row8(xh, base, lh, c);
            load_row8(xl, base, lh - 1, c);
            float p0, p1; dot2(xh, xl, p0, p1);
            float b0, b1; coef2(p0, p1, lh >= 1, b0, b1);
            #pragma unroll
            for (int k = 0; k < 8; k++)
                o1[t][k] = fmaf(b0, xh[k], fmaf(b1, xl[k], xh[k]));
        }
        float o2[2][8];
        #pragma unroll
        for (int t = 0; t < 2; t++) {
            int lh = l - 4 * t;
            float p0, p1; dot2(o1[2 * t], o1[2 * t + 1], p0, p1);
            float b0, b1; coef2(p0, p1, lh >= 2, b0, b1);
            #pragma unroll
            for (int k = 0; k < 8; k++)
                o2[t][k] = fmaf(b0, o1[2 * t][k], fmaf(b1, o1[2 * t + 1][k], o1[2 * t][k]));
        }
        float p0, p1; dot2(o2[0], o2[1], p0, p1);
        coef2(p0, p1, l >= 4, a0, a1);

        float out[8];
        #pragma unroll
        for (int k = 0; k < 8; k++)
            out[k] = fmaf(a0, o2[0][k], fmaf(a1, o2[1][k], o2[0][k]));
        float* g = g_mid + ((size_t)b * L_ + l) * D_ + c;
        *(float4*)(g)     = make_float4(out[0], out[1], out[2], out[3]);
        *(float4*)(g + 4) = make_float4(out[4], out[5], out[6], out[7]);
    }

    // ---- stream the 4KB attn row (zeros + 2 injected values) ----
    const int c0 = l;
    const int c1 = l - d;
    float4* dst = (float4*)(attn_out + (size_t)row * L_);
    #pragma unroll
    for (int s = 0; s < 8; s++) {
        int q = lane + (s << 5);
        float4 v = make_float4(0.f, 0.f, 0.f, 0.f);
        if ((c0 >> 2) == q)              ((float*)&v)[c0 & 3] = a0;
        if (c1 >= 0 && (c1 >> 2) == q)   ((float*)&v)[c1 & 3] = a1;
        __stcs(dst + q, v);
    }
}

// =====================================================================
// Kernel 2: o = g_mid[:,16:] @ W^T + bias + residual   (tf32 mma.sync)
// M=16128, N=256, K=256 ; block tile 128x128, 8 warps (4x2) of 32x64
// =====================================================================
#define GBM 128
#define GBN 128
#define GBK 32
#define SST 36    // smem k-stride: bank = (4*gid + tig), conflict-free

__device__ __forceinline__ unsigned f2tf32(float x) {
    unsigned u;
    asm("cvt.rna.tf32.f32 %0, %1;" : "=r"(u) : "f"(x));
    return u;
}

__device__ __forceinline__ void mma_tf32(float* c, const unsigned* a, const unsigned* b) {
    asm volatile(
        "mma.sync.aligned.m16n8k8.row.col.f32.tf32.tf32.f32 "
        "{%0,%1,%2,%3}, {%4,%5,%6,%7}, {%8,%9}, {%0,%1,%2,%3};"
        : "+f"(c[0]), "+f"(c[1]), "+f"(c[2]), "+f"(c[3])
        : "r"(a[0]), "r"(a[1]), "r"(a[2]), "r"(a[3]), "r"(b[0]), "r"(b[1]));
}

__global__ void __launch_bounds__(256)
gemm_tf32_kernel(const float* __restrict__ W, const float* __restrict__ bias,
                 const float* __restrict__ inp, float* __restrict__ o_out)
{
    __shared__ unsigned As[GBM * SST];   // As[row][k]
    __shared__ unsigned Bs[GBN * SST];   // Bs[col][k]

    const int tid  = threadIdx.x;
    const int m0   = blockIdx.x * GBM;
    const int n0   = blockIdx.y * GBN;
    const int wid  = tid >> 5;
    const int lane = tid & 31;
    const int warp_m = wid & 3;    // 4 warps in M (32 rows each)
    const int warp_n = wid >> 2;   // 2 warps in N (64 cols each)
    const int gid = lane >> 2;
    const int tig = lane & 3;

    float acc[2][8][4];
    #pragma unroll
    for (int i = 0; i < 2; i++)
        #pragma unroll
        for (int j = 0; j < 8; j++)
            #pragma unroll
            for (int k = 0; k < 4; k++) acc[i][j][k] = 0.f;

    for (int kc = 0; kc < 256; kc += GBK) {
        __syncthreads();
        // A tile: 128 rows x 32 k
        #pragma unroll
        for (int it = 0; it < 4; it++) {
            int idx = tid + it * 256;
            int r   = idx >> 3;
            int q   = idx & 7;
            int m   = m0 + r;
            int bb  = m / LQ_;
            int l   = m - bb * LQ_ + PAST_;
            float4 v = *(const float4*)(g_mid + ((size_t)bb * L_ + l) * D_ + kc + q * 4);
            uint4 u = make_uint4(f2tf32(v.x), f2tf32(v.y), f2tf32(v.z), f2tf32(v.w));
            *(uint4*)(As + r * SST + q * 4) = u;
        }
        // B tile: 128 cols x 32 k
        #pragma unroll
        for (int it = 0; it < 4; it++) {
            int idx = tid + it * 256;
            int n   = idx >> 3;
            int q   = idx & 7;
            float4 v = *(const float4*)(W + (size_t)(n0 + n) * 256 + kc + q * 4);
            uint4 u = make_uint4(f2tf32(v.x), f2tf32(v.y), f2tf32(v.z), f2tf32(v.w));
            *(uint4*)(Bs + n * SST + q * 4) = u;
        }
        __syncthreads();

        #pragma unroll
        for (int kk = 0; kk < GBK; kk += 8) {
            unsigned a[2][4], bq[8][2];
            #pragma unroll
            for (int mt = 0; mt < 2; mt++) {
                int r = warp_m * 32 + mt * 16 + gid;
                a[mt][0] = As[r * SST + kk + tig];
                a[mt][1] = As[(r + 8) * SST + kk + tig];
                a[mt][2] = As[r * SST + kk + tig + 4];
                a[mt][3] = As[(r + 8) * SST + kk + tig + 4];
            }
            #pragma unroll
            for (int nt = 0; nt < 8; nt++) {
                int cix = warp_n * 64 + nt * 8 + gid;
                bq[nt][0] = Bs[cix * SST + kk + tig];
                bq[nt][1] = Bs[cix * SST + kk + tig + 4];
            }
            #pragma unroll
            for (int mt = 0; mt < 2; mt++)
                #pragma unroll
                for (int nt = 0; nt < 8; nt++)
                    mma_tf32(acc[mt][nt], a[mt], bq[nt]);
        }
    }

    // Epilogue: + bias + residual inp[b, lq+16, col&63]; streaming stores
    #pragma unroll
    for (int mt = 0; mt < 2; mt++) {
        #pragma unroll
        for (int half = 0; half < 2; half++) {
            int m  = m0 + warp_m * 32 + mt * 16 + gid + half * 8;
            int bb = m / LQ_;
            int lq = m - bb * LQ_;
            const float* res = inp + ((size_t)bb * L_ + lq + PAST_) * D_;
            float* orow = o_out + (size_t)m * 256;
            #pragma unroll
            for (int nt = 0; nt < 8; nt++) {
                int col = n0 + warp_n * 64 + nt * 8 + 2 * tig;
                float v0 = acc[mt][nt][half * 2 + 0] + bias[col]     + res[col & 63];
                float v1 = acc[mt][nt][half * 2 + 1] + bias[col + 1] + res[(col + 1) & 63];
                __stcs((float2*)(orow + col), make_float2(v0, v1));
            }
        }
    }
}

extern "C" void kernel_launch(void* const* d_in, const int* in_sizes, int n_in,
                              void* d_out, int out_size)
{
    const float* inp  = (const float*)d_in[0];
    const float* W    = (const float*)d_in[1];
    const float* bias = (const float*)d_in[2];
    // d_in[3] = masks : compile-time structure, unused

    float* out  = (float*)d_out;           // o : (16, 1008, 4, 64)
    float* attn = out + O_ELEMS;           // attn_stack : (16, 3, 1024, 1024)

    fill_kernel<<<(B_ * NL_ * L_) / 8, 256>>>(inp, attn);
    gemm_tf32_kernel<<<dim3((B_ * LQ_) / GBM, 256 / GBN), 256>>>(W, bias, inp, out);
}